// round 10
// baseline (speedup 1.0000x reference)
#include <cuda_runtime.h>
#include <math_constants.h>
#include <string.h>

#define NSEQ 16          // B*H
#define SEQL 1024        // L
#define DIM  64          // D
#define CHK  128         // chunk size
#define NCHK (SEQL/CHK)  // 8
#define D2   128         // 2*DIM
#define NBLK (NSEQ*NCHK) // 128 blocks

__device__ float g_S[NSEQ*NCHK*D2*DIM];
__device__ float g_z[NSEQ*NCHK*D2];
__device__ unsigned int g_bar;   // zero-init; monotone across replays

__device__ __forceinline__ float4 relu4(float4 a){
    a.x = fmaxf(a.x,0.f); a.y = fmaxf(a.y,0.f);
    a.z = fmaxf(a.z,0.f); a.w = fmaxf(a.w,0.f);
    return a;
}
typedef unsigned long long u64c;
__device__ __forceinline__ u64c ffma2(u64c a, u64c b, u64c c){
    u64c d;
    asm("fma.rn.f32x2 %0, %1, %2, %3;" : "=l"(d) : "l"(a), "l"(b), "l"(c));
    return d;
}
// compiler-visible packs: free when halves come from aligned vector loads
__device__ __forceinline__ u64c pk(float x, float y){
    float2 t = make_float2(x, y); u64c r; memcpy(&r, &t, 8); return r;
}
__device__ __forceinline__ u64c dupf(float x){ return pk(x, x); }
__device__ __forceinline__ float2 up(u64c d){
    float2 t; memcpy(&t, &d, 8); return t;
}

__device__ __forceinline__ void grid_barrier() {
    __threadfence();
    __syncthreads();
    if (threadIdx.x == 0) {
        unsigned gen = atomicAdd(&g_bar, 1u);
        unsigned target = (gen / NBLK + 1u) * NBLK;
        while (atomicAdd(&g_bar, 0u) < target) { }
    }
    __syncthreads();
    __threadfence();
}

// ---------------------------------------------------------------------------
// Fused kernel. grid = 128 (one block per (seq, chunk)), block = 1024.
// ---------------------------------------------------------------------------
__global__ void __launch_bounds__(1024,1)
fused_cos_attn(const float* __restrict__ q, const float* __restrict__ k,
               const float* __restrict__ v, float* __restrict__ out) {
    const int blk = blockIdx.x;
    const int n = blk >> 3, c = blk & 7;
    extern __shared__ float sm[];
    float* qextT = sm;                       // [128 d'][132]
    float* kbuf  = qextT + 128*132;          // kextT [d'][132]; At overlay later
    float* V     = kbuf + 128*132 + 32;      // [128 j][68]
    float* U     = V + 128*68;               // [128 d'][68]
    float* zext  = U + 128*68;               // 128
    float* den   = zext + 128;               // 128
    float* dscr  = den + 128;                // 512
    const int tid = threadIdx.x;
    const size_t base = ((size_t)n*SEQL + (size_t)c*CHK)*DIM;
    const float4* q4 = (const float4*)(q + base);
    const float4* k4 = (const float4*)(k + base);
    const float4* v4 = (const float4*)(v + base);

    // ---- Stage q,k,v: qextT/kextT transposed [d'][j], V row-major ----
    {
        const int j = tid & 127;
        const float ang = 1.5707963268f * (float)(c*CHK + j + 1) * (1.f/(float)SEQL);
        const float s = __sinf(ang), cc = __cosf(ang);
        #pragma unroll
        for (int it = 0; it < 2; it++) {
            int f = (tid >> 7) + 8*it;       // 0..15
            float4 qq = relu4(q4[j*16 + f]);
            float4 kk = relu4(k4[j*16 + f]);
            float4 vv = relu4(v4[j*16 + f]);
            int d = 4*f;
            qextT[(d+0)*132 + j] = qq.x*s;  qextT[(d+64)*132 + j] = qq.x*cc;
            qextT[(d+1)*132 + j] = qq.y*s;  qextT[(d+65)*132 + j] = qq.y*cc;
            qextT[(d+2)*132 + j] = qq.z*s;  qextT[(d+66)*132 + j] = qq.z*cc;
            qextT[(d+3)*132 + j] = qq.w*s;  qextT[(d+67)*132 + j] = qq.w*cc;
            kbuf[(d+0)*132 + j] = kk.x*s;   kbuf[(d+64)*132 + j] = kk.x*cc;
            kbuf[(d+1)*132 + j] = kk.y*s;   kbuf[(d+65)*132 + j] = kk.y*cc;
            kbuf[(d+2)*132 + j] = kk.z*s;   kbuf[(d+66)*132 + j] = kk.z*cc;
            kbuf[(d+3)*132 + j] = kk.w*s;   kbuf[(d+67)*132 + j] = kk.w*cc;
            *(float4*)&V[j*68 + d] = vv;
        }
    }
    __syncthreads();

    // ---- z[d'] = sum_j kextT[d'][j] ----
    if (tid < D2) {
        float zz = 0.f;
        #pragma unroll 8
        for (int j = 0; j < CHK; j++) zz += kbuf[tid*132 + j];
        g_z[blk*D2 + tid] = zz;
    }

    // ---- Chunk-state GEMM: S[d'][m] = sum_j kextT[d'][j]*V[j][m] (2d' x 4m) --
    {
        const int td = tid >> 4, tm = tid & 15;   // 64 x 16
        const int d0 = td*2;
        const float4* V4 = (const float4*)V;
        u64c acc[2][2];                           // [d' row][m-pair]
        acc[0][0]=acc[0][1]=acc[1][0]=acc[1][1]=pk(0.f,0.f);

        #pragma unroll 2
        for (int jb = 0; jb < CHK; jb += 4) {
            float4 kr0 = *(const float4*)&kbuf[ d0   *132 + jb];
            float4 kr1 = *(const float4*)&kbuf[(d0+1)*132 + jb];
            float k0a[4] = {kr0.x,kr0.y,kr0.z,kr0.w};
            float k1a[4] = {kr1.x,kr1.y,kr1.z,kr1.w};
            #pragma unroll
            for (int i = 0; i < 4; i++) {
                float4 vv = V4[(jb+i)*17 + tm];
                u64c vp0 = pk(vv.x,vv.y), vp1 = pk(vv.z,vv.w);
                u64c k0d = dupf(k0a[i]), k1d = dupf(k1a[i]);
                acc[0][0] = ffma2(k0d, vp0, acc[0][0]);
                acc[0][1] = ffma2(k0d, vp1, acc[0][1]);
                acc[1][0] = ffma2(k1d, vp0, acc[1][0]);
                acc[1][1] = ffma2(k1d, vp1, acc[1][1]);
            }
        }
        float4* oS = (float4*)(g_S + (size_t)blk*D2*DIM);
        #pragma unroll
        for (int r = 0; r < 2; r++) {
            float2 a0 = up(acc[r][0]), a1 = up(acc[r][1]);
            oS[(d0+r)*16 + tm] = make_float4(a0.x, a0.y, a1.x, a1.y);
        }
    }

    grid_barrier();

    // ---- Prefix state U = sum of chunks 0..c-1 ----
    {
        float4 ua[2];
        ua[0] = make_float4(0.f,0.f,0.f,0.f);
        ua[1] = make_float4(0.f,0.f,0.f,0.f);
        const float4* gSn = (const float4*)(g_S + (size_t)(n*NCHK)*D2*DIM);
        for (int cc = 0; cc < c; cc++) {
            const float4* p = gSn + (size_t)cc*2048;
            #pragma unroll
            for (int it = 0; it < 2; it++) {
                float4 t = p[tid + 1024*it];
                ua[it].x += t.x; ua[it].y += t.y; ua[it].z += t.z; ua[it].w += t.w;
            }
        }
        float4* U4w = (float4*)U;
        #pragma unroll
        for (int it = 0; it < 2; it++) {
            int i4 = tid + 1024*it;
            U4w[(i4 >> 4)*17 + (i4 & 15)] = ua[it];
        }
        if (tid < D2) {
            float zz = 0.f;
            for (int cc = 0; cc < c; cc++) zz += g_z[(n*NCHK + cc)*D2 + tid];
            zext[tid] = zz;
        }
    }

    const float4* qT4 = (const float4*)qextT;
    const float4* kT4 = (const float4*)kbuf;

    // ---- Phase A: A[l][j] = sum_d' qext[d'][l]*kext[d'][j]; 4l x 4j tiles ----
    // warp tile 16l x 32j; warp (wl,wj) active iff wj*32 <= wl*16+15.
    const int wid = tid >> 5, lane = tid & 31;
    const int wl = wid >> 2, wj = wid & 3;
    const int tl = wl*4 + (lane >> 3);       // 0..31, l0 = 4*tl
    const int tj = wj*8 + (lane & 7);        // 0..31, j0 = 4*tj
    const int l0 = tl*4, j0 = tj*4;
    u64c a2[4][2];                            // [jj][l-pair]
    #pragma unroll
    for (int jj = 0; jj < 4; jj++) { a2[jj][0] = pk(0.f,0.f); a2[jj][1] = pk(0.f,0.f); }

    if (wj*32 <= wl*16 + 15) {
        #pragma unroll 4
        for (int dp = 0; dp < D2; dp++) {
            float4 qa = qT4[dp*33 + tl];
            float4 kA = kT4[dp*33 + tj];
            u64c qp0 = pk(qa.x,qa.y), qp1 = pk(qa.z,qa.w);
            float kv[4] = {kA.x,kA.y,kA.z,kA.w};
            #pragma unroll
            for (int jj = 0; jj < 4; jj++) {
                u64c kd = dupf(kv[jj]);
                a2[jj][0] = ffma2(kd, qp0, a2[jj][0]);
                a2[jj][1] = ffma2(kd, qp1, a2[jj][1]);
            }
        }
    }
    __syncthreads();

    // Masked transposed store At[j][l], XOR-swizzled float4 groups.
    float4* At4 = (float4*)kbuf;
    #pragma unroll
    for (int jj = 0; jj < 4; jj++) {
        int j = j0 + jj;
        int swz = (j >> 3) & 7;
        float2 p0 = up(a2[jj][0]), p1 = up(a2[jj][1]);
        float w0 = (j <= l0    ) ? p0.x : 0.f;
        float w1 = (j <= l0 + 1) ? p0.y : 0.f;
        float w2 = (j <= l0 + 2) ? p1.x : 0.f;
        float w3 = (j <= l0 + 3) ? p1.y : 0.f;
        At4[j*33 + (tl ^ swz)] = make_float4(w0, w1, w2, w3);
    }
    __syncthreads();

    // ---- Denominator (512 threads, 4 partials per l) ----
    if (tid < 512) {
        const int l = tid >> 2, part = tid & 3;
        float dd = 0.f;
        const int jlo = part*32;
        const int jhi = min(jlo + 32, l + 1);
        for (int j = jlo; j < jhi; j++) {
            int swz = (j >> 3) & 7;
            dd += kbuf[j*132 + 4*((l>>2) ^ swz) + (l & 3)];
        }
        #pragma unroll 8
        for (int dp = jlo; dp < jlo + 32; dp++)
            dd = fmaf(qextT[dp*132 + l], zext[dp], dd);
        dscr[tid] = dd;
    }
    __syncthreads();
    if (tid < CHK)
        den[tid] = fmaxf(dscr[4*tid] + dscr[4*tid+1] + dscr[4*tid+2] + dscr[4*tid+3], 1e-6f);
    __syncthreads();

    // ---- Phase B: out = A*V + qext*U; 4l x 2m tiles ----
    const int lg = tid >> 5;                 // 0..31, lB0 = 4*lg
    const int mg = tid & 31;                 // 0..31, m0 = 2*mg
    const int lB0 = lg*4, m0 = 2*mg;
    u64c o2[2][2];                            // [l-pair][m]
    o2[0][0]=o2[0][1]=o2[1][0]=o2[1][1]=pk(0.f,0.f);

    const float2* V2 = (const float2*)V;     // stride 34 float2
    const float2* U2 = (const float2*)U;

    const int jmax = lB0 + 4;
    #pragma unroll 4
    for (int j = 0; j < jmax; j++) {
        int swz = (j >> 3) & 7;
        float4 A0 = At4[j*33 + (lg ^ swz)];
        float2 vv = V2[j*34 + mg];
        u64c ap0 = pk(A0.x,A0.y), ap1 = pk(A0.z,A0.w);
        u64c vd0 = dupf(vv.x), vd1 = dupf(vv.y);
        o2[0][0] = ffma2(ap0, vd0, o2[0][0]);
        o2[0][1] = ffma2(ap0, vd1, o2[0][1]);
        o2[1][0] = ffma2(ap1, vd0, o2[1][0]);
        o2[1][1] = ffma2(ap1, vd1, o2[1][1]);
    }
    #pragma unroll 4
    for (int dp = 0; dp < D2; dp++) {
        float4 qa = qT4[dp*33 + lg];
        float2 uu = U2[dp*34 + mg];
        u64c qp0 = pk(qa.x,qa.y), qp1 = pk(qa.z,qa.w);
        u64c ud0 = dupf(uu.x), ud1 = dupf(uu.y);
        o2[0][0] = ffma2(qp0, ud0, o2[0][0]);
        o2[0][1] = ffma2(qp0, ud1, o2[0][1]);
        o2[1][0] = ffma2(qp1, ud0, o2[1][0]);
        o2[1][1] = ffma2(qp1, ud1, o2[1][1]);
    }

    float* ob = out + base;
    {
        float2 p00 = up(o2[0][0]), p01 = up(o2[0][1]);
        float2 p10 = up(o2[1][0]), p11 = up(o2[1][1]);
        float r0 = 1.f/den[lB0], r1 = 1.f/den[lB0+1];
        float r2 = 1.f/den[lB0+2], r3 = 1.f/den[lB0+3];
        *(float2*)&ob[(lB0+0)*64 + m0] = make_float2(p00.x*r0, p01.x*r0);
        *(float2*)&ob[(lB0+1)*64 + m0] = make_float2(p00.y*r1, p01.y*r1);
        *(float2*)&ob[(lB0+2)*64 + m0] = make_float2(p10.x*r2, p11.x*r2);
        *(float2*)&ob[(lB0+3)*64 + m0] = make_float2(p10.y*r3, p11.y*r3);
    }
}

extern "C" void kernel_launch(void* const* d_in, const int* in_sizes, int n_in,
                              void* d_out, int out_size) {
    const float* q = (const float*)d_in[0];
    const float* k = (const float*)d_in[1];
    const float* v = (const float*)d_in[2];
    float* out = (float*)d_out;

    const int smem = (128*132 + 128*132 + 32 + 2*128*68 + 128 + 128 + 512) * 4; // 208,000 B
    cudaFuncSetAttribute(fused_cos_attn, cudaFuncAttributeMaxDynamicSharedMemorySize, smem);
    fused_cos_attn<<<NBLK, 1024, smem>>>(q, k, v, out);
}